// round 2
// baseline (speedup 1.0000x reference)
#include <cuda_runtime.h>

// Problem constants
#define NBATCH 32
#define NCHAN  3
#define NIMG   (NBATCH * NCHAN)   // 96 independent 512x512 images
#define H      512
#define W      512
#define PADT   10                 // top/bottom zero pad rows
#define HP     (H + 2 * PADT)     // 532 padded rows
#define WP     544                // padded row width: 12 left zeros, 512 body, 20 right zeros
#define KS     21
#define KTAPS  (KS * KS)          // 441

// Padded-input scratch (x and y padded): g_xpad[img][py][px]
__device__ float g_xpad[(size_t)NIMG * HP * WP];

// ---- packed fp32x2 helpers ----------------------------------------------
__device__ __forceinline__ void ffma2(unsigned long long& d,
                                      unsigned long long a,
                                      unsigned long long b) {
    asm("fma.rn.f32x2 %0, %1, %2, %0;" : "+l"(d) : "l"(a), "l"(b));
}

__device__ __forceinline__ unsigned long long pk(float lo, float hi) {
    unsigned long long r;
    asm("mov.b64 %0, {%1, %2};" : "=l"(r) : "f"(lo), "f"(hi));
    return r;
}

__device__ __forceinline__ void unpk(unsigned long long v, float& lo, float& hi) {
    asm("mov.b64 {%0, %1}, %2;" : "=f"(lo), "=f"(hi) : "l"(v));
}

// ---- kernel 1: zero-pad x into g_xpad (x and y) --------------------------
// px = gx + 12 (body px 12..523), py = gy + 10 (body py 10..521).
__global__ void prepad_kernel(const float* __restrict__ x) {
    int idx = blockIdx.x * 256 + threadIdx.x;        // one float4 per thread
    int q   = idx % (WP / 4);                        // quad within padded row
    int ry  = idx / (WP / 4);                        // img*HP + py
    int py  = ry % HP;
    int img = ry / HP;
    float4 val = make_float4(0.f, 0.f, 0.f, 0.f);
    if (q >= 3 && q < 131 && py >= PADT && py < PADT + H) {
        val = *reinterpret_cast<const float4*>(
            x + ((size_t)img * H + (py - PADT)) * W + q * 4 - 12);
    }
    *reinterpret_cast<float4*>(g_xpad + (size_t)ry * WP + q * 4) = val;
}

// ---- kernel 2: depthwise conv, row-pair packed FFMA2 ---------------------
// Accumulator acc[c] = (out[Y][X+c], out[Y+1][X+c]).
// Fused diagonal tap table: kp[r][jj] = (k[r][jj-1], k[r-1][jj]) (OOR -> 0).
// Per input row r (0..21): for jj 0..21:
//   acc[c] += (x[iy][X+c+jj-11], x[iy][X+c+jj-10]) * kp[r][jj]
// lane0: k[r][jj-1]   * x[.., X+c+(jj-1)-10]  -> out[Y][X+c]     (dy=r)
// lane1: k[r-1][jj]   * x[.., X+c+jj-10]      -> out[Y+1][X+c]   (dy=r-1)
//
// CTA: 128 threads = 4 col-groups (8 cols each -> 32 cols) x 32 row-pairs (64 rows).
__global__ __launch_bounds__(128) void conv_kernel(const float* __restrict__ d_k,
                                                   float* __restrict__ d_out) {
    __shared__ float2 kp[22 * 22];

    const int tid = threadIdx.x;
    const int img = blockIdx.z;

    // build fused tap table for this image's kernel (kernel idx = img/3)
    const float* kptr = d_k + (size_t)(img / NCHAN) * KTAPS;
    for (int i = tid; i < 22 * 22; i += 128) {
        int r  = i / 22;
        int jj = i % 22;
        float lo = (r <= 20 && jj >= 1) ? kptr[r * KS + jj - 1] : 0.f;
        float hi = (r >= 1 && jj <= 20) ? kptr[(r - 1) * KS + jj] : 0.f;
        kp[i] = make_float2(lo, hi);
    }
    __syncthreads();

    const int lane_x = tid & 3;                       // 4 col groups
    const int pair_y = tid >> 2;                      // 32 row pairs
    const int X = blockIdx.x * 32 + lane_x * 8;       // first of 8 output cols
    const int Y = blockIdx.y * 64 + pair_y * 2;       // output row pair (Y, Y+1)

    // fl2[s] = g_xpad[img][Y + r][X + s]; a-pair offset o = c + jj + 1 in [1,29],
    // pair = (fl2[o], fl2[o+1]) -> uses fl2[1..30]. Load fl2[0..31]: 8 aligned LDG.128.
    const float* base = g_xpad + ((size_t)img * HP + Y) * WP + X;

    unsigned long long acc[8];
#pragma unroll
    for (int c = 0; c < 8; ++c) acc[c] = 0ull;

#pragma unroll 2
    for (int r = 0; r < 22; ++r) {
        const float4* src = reinterpret_cast<const float4*>(base + (size_t)r * WP);
        float4 v[8];
#pragma unroll
        for (int j = 0; j < 8; ++j) v[j] = src[j];

        float fl[32];
#pragma unroll
        for (int j = 0; j < 8; ++j) {
            fl[4 * j + 0] = v[j].x; fl[4 * j + 1] = v[j].y;
            fl[4 * j + 2] = v[j].z; fl[4 * j + 3] = v[j].w;
        }

        // even-offset pairs ge[m] = (fl[2m], fl[2m+1]) (align with load quads),
        // odd-offset pairs  go[m] = (fl[2m+1], fl[2m+2])
        unsigned long long ge[15], go[15];
#pragma unroll
        for (int m = 1; m < 15; ++m) ge[m] = pk(fl[2 * m], fl[2 * m + 1]);
#pragma unroll
        for (int m = 0; m < 15; ++m) go[m] = pk(fl[2 * m + 1], fl[2 * m + 2]);

        const unsigned long long* krow =
            reinterpret_cast<const unsigned long long*>(&kp[r * 22]);
#pragma unroll
        for (int jj = 0; jj < 22; ++jj) {
            unsigned long long kk = krow[jj];
#pragma unroll
            for (int c = 0; c < 8; ++c) {
                const int o = c + jj + 1;
                unsigned long long a = (o & 1) ? go[(o - 1) >> 1] : ge[o >> 1];
                ffma2(acc[c], a, kk);
            }
        }
    }

    // unpack + store: both rows aligned at col X
    float lo[8], hi[8];
#pragma unroll
    for (int c = 0; c < 8; ++c) unpk(acc[c], lo[c], hi[c]);

    float* outp = d_out + ((size_t)img * H + Y) * W + X;
    reinterpret_cast<float4*>(outp)[0]     = make_float4(lo[0], lo[1], lo[2], lo[3]);
    reinterpret_cast<float4*>(outp)[1]     = make_float4(lo[4], lo[5], lo[6], lo[7]);
    reinterpret_cast<float4*>(outp + W)[0] = make_float4(hi[0], hi[1], hi[2], hi[3]);
    reinterpret_cast<float4*>(outp + W)[1] = make_float4(hi[4], hi[5], hi[6], hi[7]);
}

// ---- launch --------------------------------------------------------------
extern "C" void kernel_launch(void* const* d_in, const int* in_sizes, int n_in,
                              void* d_out, int out_size) {
    const float* x = (const float*)d_in[0];   // (32,3,512,512) fp32
    const float* k = (const float*)d_in[1];   // (32,1,21,21)  fp32
    float* out = (float*)d_out;

    // 1) pad input (x and y) into scratch
    const int total_quads = NIMG * HP * (WP / 4);    // 96*532*136 = 6,945,792
    prepad_kernel<<<total_quads / 256, 256>>>(x);

    // 2) main conv: grid (16, 8, 96)
    dim3 grid(W / 32, H / 64, NIMG);
    conv_kernel<<<grid, 128>>>(k, out);
}